// round 15
// baseline (speedup 1.0000x reference)
#include <cuda_runtime.h>
#include <cstdint>

// Problem constants (fixed by setup_inputs)
#define BATCH   8
#define LEN     4096
#define ROWS    (BATCH * LEN)      // 32768
#define NST     256                // state/input/output size
#define KHALF   128                // number of 2x2 complex channels
#define LC      64                 // scan chunk length == GEMM block M tile
#define CHUNKS  (ROWS / LC)        // 512
#define CPB     (LEN / LC)         // 64 chunks per batch sequence

// Scratch (device globals: no allocation allowed)
__device__ float g_x1[ROWS * NST];     // u @ B (f32)
__device__ float g_s [CHUNKS * NST];   // per-chunk local scan results
__device__ float g_in[CHUNKS * NST];   // per-chunk incoming states
__device__ float g_Bt[NST * NST];      // B^T, tf32(rna)  [n][k]
__device__ float g_Ct[NST * NST];      // C^T, tf32(rna)  [n][k]

// ---------------------------------------------------------------------------
// helpers
// ---------------------------------------------------------------------------
__device__ __forceinline__ uint32_t f2tf(float f) {
    uint32_t r;
    asm("cvt.rna.tf32.f32 %0, %1;" : "=r"(r) : "f"(f));
    return r;
}

__device__ __forceinline__ void mma4(float* d, const uint32_t* a, uint32_t b0, uint32_t b1) {
    asm volatile(
        "mma.sync.aligned.m16n8k8.row.col.f32.tf32.tf32.f32 "
        "{%0,%1,%2,%3}, {%4,%5,%6,%7}, {%8,%9}, {%0,%1,%2,%3};\n"
        : "+f"(d[0]), "+f"(d[1]), "+f"(d[2]), "+f"(d[3])
        : "r"(a[0]), "r"(a[1]), "r"(a[2]), "r"(a[3]), "r"(b0), "r"(b1));
}

__device__ __forceinline__ void ldsm4(uint32_t* r, uint32_t addr) {
    asm volatile("ldmatrix.sync.aligned.m8n8.x4.shared.b16 {%0,%1,%2,%3}, [%4];"
                 : "=r"(r[0]), "=r"(r[1]), "=r"(r[2]), "=r"(r[3]) : "r"(addr));
}

__device__ __forceinline__ void cp16(uint32_t smem, const void* gmem) {
    asm volatile("cp.async.ca.shared.global [%0], [%1], 16;\n" :: "r"(smem), "l"(gmem));
}

// ===========================================================================
// prep: weights -> transposed tf32(rna) copies. Coalesced read, strided write.
// ===========================================================================
__global__ void prep_wt(const float* __restrict__ B, const float* __restrict__ C) {
    int i = blockIdx.x * blockDim.x + threadIdx.x;   // i = k*256 + n
    int k = i >> 8, n = i & 255;
    g_Bt[n * NST + k] = __uint_as_float(f2tf(B[i]));
    g_Ct[n * NST + k] = __uint_as_float(f2tf(C[i]));
}

// ===========================================================================
// K1: gemm1 (x1 = u @ B) fused with per-chunk zero-init local scan -> g_s.
// Block tile 64x256, BK=16, 4 warps, warp tile 64x64.
// A (u) staged raw via cp.async then cvt.rna'd in place; B^T preconverted.
// Fragments via ldmatrix.x4.b16 (stride-20 rows -> conflict-free).
// SMEM: As[2][64][20] + BsT[2][256][20] = 51200 B; xs alias 64x258 = 66048 B.
// ===========================================================================
__global__ void __launch_bounds__(128, 3) gemm_scan1(const float* __restrict__ u,
                                                     const float* __restrict__ Arot)
{
    extern __shared__ float sm1[];
    float (*As)[64][20]  = (float(*)[64][20])sm1;            // [2][64][20]
    float (*Bs)[256][20] = (float(*)[256][20])(sm1 + 2560);  // [2][256][20]
    float (*xs)[258]     = (float(*)[258])sm1;               // alias (epilogue)

    const int tid  = threadIdx.x;
    const int warp = tid >> 5;
    const int lane = tid & 31;
    const int g = lane >> 2, t = lane & 3;
    const long mbase = (long)blockIdx.x * 64;
    const int nb0 = warp * 64;

    // ldmatrix per-lane address components
    const int aRow = (lane & 7) + ((lane >> 3) & 1) * 8;  // within 16-row block
    const int aCol = (lane >> 4) * 4;                     // 0 or 4
    const int bRow = (lane & 7) + (lane >> 4) * 8;        // within 16-n block
    const int bCol = ((lane >> 3) & 1) * 4;               // 0 or 4

    auto loadTiles = [&](int k0, int st) {
        #pragma unroll
        for (int p = 0; p < 2; ++p) {                     // A: 256 x 16B
            int ch = tid + p * 128;
            int r = ch >> 2, c4 = (ch & 3) * 4;
            cp16((uint32_t)__cvta_generic_to_shared(&As[st][r][c4]),
                 u + (mbase + r) * NST + k0 + c4);
        }
        #pragma unroll
        for (int p = 0; p < 8; ++p) {                     // B^T: 1024 x 16B
            int ch = tid + p * 128;
            int n = ch >> 2, c4 = (ch & 3) * 4;
            cp16((uint32_t)__cvta_generic_to_shared(&Bs[st][n][c4]),
                 g_Bt + n * NST + k0 + c4);
        }
        asm volatile("cp.async.commit_group;\n");
    };

    float acc[4][8][4];
    #pragma unroll
    for (int i = 0; i < 4; ++i)
        #pragma unroll
        for (int j = 0; j < 8; ++j)
            #pragma unroll
            for (int q = 0; q < 4; ++q) acc[i][j][q] = 0.f;

    loadTiles(0, 0);

    for (int it = 0; it < 16; ++it) {
        asm volatile("cp.async.wait_group 0;\n");
        __syncthreads();
        if (it + 1 < 16) loadTiles((it + 1) * 16, (it + 1) & 1);

        const int st = it & 1;
        // convert the A stage in place: f32 -> tf32(rna)
        #pragma unroll
        for (int i2 = 0; i2 < 2; ++i2) {
            int id = tid + i2 * 128;                      // 0..255
            int r = id >> 2, c = (id & 3) * 4;
            float4 v = *(float4*)&As[st][r][c];
            v.x = __uint_as_float(f2tf(v.x));
            v.y = __uint_as_float(f2tf(v.y));
            v.z = __uint_as_float(f2tf(v.z));
            v.w = __uint_as_float(f2tf(v.w));
            *(float4*)&As[st][r][c] = v;
        }
        __syncthreads();

        const uint32_t sA = (uint32_t)__cvta_generic_to_shared(&As[st][0][0]);
        const uint32_t sB = (uint32_t)__cvta_generic_to_shared(&Bs[st][0][0]);
        #pragma unroll
        for (int kk = 0; kk < 16; kk += 8) {
            uint32_t bq[4][4];
            #pragma unroll
            for (int q = 0; q < 4; ++q)
                ldsm4(bq[q], sB + ((nb0 + 16 * q + bRow) * 20 + kk + bCol) * 4);
            #pragma unroll
            for (int ip = 0; ip < 2; ++ip) {
                uint32_t aa[2][4];
                #pragma unroll
                for (int ii = 0; ii < 2; ++ii)
                    ldsm4(aa[ii], sA + (((ip * 2 + ii) * 16 + aRow) * 20 + kk + aCol) * 4);
                #pragma unroll
                for (int ii = 0; ii < 2; ++ii) {
                    int i = ip * 2 + ii;
                    #pragma unroll
                    for (int q = 0; q < 4; ++q) {
                        mma4(acc[i][2 * q],     aa[ii], bq[q][0], bq[q][1]);
                        mma4(acc[i][2 * q + 1], aa[ii], bq[q][2], bq[q][3]);
                    }
                }
            }
        }
    }
    __syncthreads();   // before epilogue writes alias the mainloop buffers

    // Epilogue: write x1 tile to gmem AND into xs (alias).
    #pragma unroll
    for (int i = 0; i < 4; ++i) {
        long r0 = mbase + i * 16 + g;
        int lr = i * 16 + g;
        #pragma unroll
        for (int j = 0; j < 8; ++j) {
            int cn = warp * 64 + j * 8 + 2 * t;
            float2 v0 = make_float2(acc[i][j][0], acc[i][j][1]);
            float2 v1 = make_float2(acc[i][j][2], acc[i][j][3]);
            *(float2*)&g_x1[r0 * NST + cn]       = v0;
            *(float2*)&g_x1[(r0 + 8) * NST + cn] = v1;
            *(float2*)&xs[lr][cn]     = v0;
            *(float2*)&xs[lr + 8][cn] = v1;
        }
    }
    __syncthreads();

    // Local scan (zero init): thread k handles complex channel k.
    {
        const int k = tid;   // 0..127
        const float wc = Arot[k * 4 + 0];
        const float ws = Arot[k * 4 + 1];
        float zr = 0.f, zi = 0.f;
        #pragma unroll 8
        for (int tt = 0; tt < LC; ++tt) {
            float2 v = *(const float2*)&xs[tt][2 * k];
            float nr = fmaf(zr, wc, fmaf(-zi, ws, v.x));
            float ni = fmaf(zr, ws, fmaf( zi, wc, v.y));
            zr = nr; zi = ni;
        }
        ((float2*)g_s)[blockIdx.x * KHALF + k] = make_float2(zr, zi);
    }
}

// ===========================================================================
// K2: carry propagation, one block per batch (SMEM-staged chain).
// ===========================================================================
__global__ void __launch_bounds__(128) scan_carry(const float* __restrict__ Arot,
                                                  const float* __restrict__ x0,
                                                  float* __restrict__ tail,
                                                  int write_tail)
{
    extern __shared__ float ss[];               // [64][256]
    const int b = blockIdx.x;
    const int k = threadIdx.x;                  // 0..127

    const float4* src = (const float4*)(g_s + (size_t)b * CPB * NST);
    float4* dst = (float4*)ss;
    #pragma unroll
    for (int i = 0; i < 32; ++i)
        dst[k + i * 128] = src[k + i * 128];
    __syncthreads();

    float Wr = Arot[k * 4 + 0];
    float Wi = Arot[k * 4 + 1];
    #pragma unroll
    for (int i = 0; i < 6; ++i) {               // w -> w^64 by squaring
        float nr = Wr * Wr - Wi * Wi;
        float ni = 2.f * Wr * Wi;
        Wr = nr; Wi = ni;
    }

    float2 z = ((const float2*)x0)[b * KHALF + k];
    float zr = z.x, zi = z.y;
    #pragma unroll 8
    for (int c = 0; c < CPB; ++c) {
        ((float2*)g_in)[(b * CPB + c) * KHALF + k] = make_float2(zr, zi);
        float2 s = ((const float2*)ss)[c * KHALF + k];
        float nr = fmaf(zr, Wr, fmaf(-zi, Wi, s.x));
        float ni = fmaf(zr, Wi, fmaf( zi, Wr, s.y));
        zr = nr; zi = ni;
    }
    if (write_tail)
        ((float2*)tail)[b * KHALF + k] = make_float2(zr, zi);
}

// ===========================================================================
// K3: fused apply-scan + gemm2 (y = x @ C).
// Scan writes x tf32(rna)-rounded into xs[64][260] (stride 260 = conflict-free
// for ldmatrix). Mainloop: A frags ldmatrix from xs, B frags ldmatrix from
// preconverted C^T (2-stage cp.async, one-ahead). Zero CVT in the loop.
// SMEM: xs 64x260 (66560 B) + Bs[2][256][20] (40960 B) = 107520 B.
// ===========================================================================
__global__ void __launch_bounds__(128) gemm_scan2(const float* __restrict__ Arot,
                                                  float* __restrict__ y)
{
    extern __shared__ float sm3[];
    float (*xs)[260]     = (float(*)[260])sm3;                 // 64 x 260
    float (*Bs)[256][20] = (float(*)[256][20])(sm3 + 64*260);  // [2][256][20]

    const int tid  = threadIdx.x;
    const int warp = tid >> 5;
    const int lane = tid & 31;
    const int g = lane >> 2, t = lane & 3;
    const int cid = blockIdx.x;
    const long mbase = (long)cid * 64;
    const int nb0 = warp * 64;

    const int aRow = (lane & 7) + ((lane >> 3) & 1) * 8;
    const int aCol = (lane >> 4) * 4;
    const int bRow = (lane & 7) + (lane >> 4) * 8;
    const int bCol = ((lane >> 3) & 1) * 4;

    auto loadB = [&](int k0, int st) {
        #pragma unroll
        for (int p = 0; p < 8; ++p) {
            int ch = tid + p * 128;
            int n = ch >> 2, c4 = (ch & 3) * 4;
            cp16((uint32_t)__cvta_generic_to_shared(&Bs[st][n][c4]),
                 g_Ct + n * NST + k0 + c4);
        }
        asm volatile("cp.async.commit_group;\n");
    };

    loadB(0, 0);   // overlap first C tile with the scan below

    // ---- apply-scan: gmem x1 -> recurrence -> xs (tf32-rounded) ----
    {
        const int k = tid;
        const float wc = Arot[k * 4 + 0];
        const float ws = Arot[k * 4 + 1];
        const float2* p = (const float2*)(g_x1 + (size_t)cid * LC * NST) + k;
        float2 z0 = ((const float2*)g_in)[cid * KHALF + k];
        float zr = z0.x, zi = z0.y;
        #pragma unroll
        for (int tt0 = 0; tt0 < LC; tt0 += 8) {
            float2 v[8];
            #pragma unroll
            for (int j = 0; j < 8; ++j)
                v[j] = p[(size_t)(tt0 + j) * (NST / 2)];
            #pragma unroll
            for (int j = 0; j < 8; ++j) {
                float nr = fmaf(zr, wc, fmaf(-zi, ws, v[j].x));
                float ni = fmaf(zr, ws, fmaf( zi, wc, v[j].y));
                zr = nr; zi = ni;
                *(float2*)&xs[tt0 + j][2 * k] =
                    make_float2(__uint_as_float(f2tf(zr)), __uint_as_float(f2tf(zi)));
            }
        }
    }

    // ---- mainloop: y_tile = xs @ C ----
    float acc[4][8][4];
    #pragma unroll
    for (int i = 0; i < 4; ++i)
        #pragma unroll
        for (int j = 0; j < 8; ++j)
            #pragma unroll
            for (int q = 0; q < 4; ++q) acc[i][j][q] = 0.f;

    const uint32_t sX = (uint32_t)__cvta_generic_to_shared(&xs[0][0]);

    for (int it = 0; it < 16; ++it) {
        asm volatile("cp.async.wait_group 0;\n");
        __syncthreads();                       // also orders scan writes (it==0)
        if (it + 1 < 16) loadB((it + 1) * 16, (it + 1) & 1);

        const int st = it & 1;
        const int k0 = it * 16;
        const uint32_t sB = (uint32_t)__cvta_generic_to_shared(&Bs[st][0][0]);
        #pragma unroll
        for (int kk = 0; kk < 16; kk += 8) {
            uint32_t bq[4][4];
            #pragma unroll
            for (int q = 0; q < 4; ++q)
                ldsm4(bq[q], sB + ((nb0 + 16 * q + bRow) * 20 + kk + bCol) * 4);
            #pragma unroll
            for (int ip = 0; ip < 2; ++ip) {
                uint32_t aa[2][4];
                #pragma unroll
                for (int ii = 0; ii < 2; ++ii)
                    ldsm4(aa[ii], sX + (((ip * 2 + ii) * 16 + aRow) * 260 + k0 + kk + aCol) * 4);
                #pragma unroll
                for (int ii = 0; ii < 2; ++ii) {
                    int i = ip * 2 + ii;
                    #pragma unroll
                    for (int q = 0; q < 4; ++q) {
                        mma4(acc[i][2 * q],     aa[ii], bq[q][0], bq[q][1]);
                        mma4(acc[i][2 * q + 1], aa[ii], bq[q][2], bq[q][3]);
                    }
                }
            }
        }
    }

    #pragma unroll
    for (int i = 0; i < 4; ++i) {
        long r0 = mbase + i * 16 + g;
        #pragma unroll
        for (int j = 0; j < 8; ++j) {
            int cn = warp * 64 + j * 8 + 2 * t;
            *(float2*)&y[r0 * NST + cn]       = make_float2(acc[i][j][0], acc[i][j][1]);
            *(float2*)&y[(r0 + 8) * NST + cn] = make_float2(acc[i][j][2], acc[i][j][3]);
        }
    }
}

// ---------------------------------------------------------------------------
// Launch: prep -> K1 -> K2 -> K3.
// Output: y (8*4096*256 f32) then new_state (8*128*2 f32), concatenated.
// ---------------------------------------------------------------------------
extern "C" void kernel_launch(void* const* d_in, const int* in_sizes, int n_in,
                              void* d_out, int out_size)
{
    const float* u  = (const float*)d_in[0];
    const float* x0 = (const float*)d_in[1];
    const float* A  = (const float*)d_in[2];
    const float* B  = (const float*)d_in[3];
    const float* C  = (const float*)d_in[4];
    float* out = (float*)d_out;

    const int YSZ = ROWS * NST;
    const int TSZ = BATCH * KHALF * 2;
    const int wt = (out_size >= YSZ + TSZ) ? 1 : 0;
    float* tail = out + YSZ;

    const int SM1 = 66048;     // xs alias dominates (As+BsT = 51200)
    const int SM2 = 65536;     // ss[64][256]
    const int SM3 = 107520;    // xs[64][260] + BsT 2-stage

    cudaFuncSetAttribute(gemm_scan1, cudaFuncAttributeMaxDynamicSharedMemorySize, SM1);
    cudaFuncSetAttribute(scan_carry, cudaFuncAttributeMaxDynamicSharedMemorySize, SM2);
    cudaFuncSetAttribute(gemm_scan2, cudaFuncAttributeMaxDynamicSharedMemorySize, SM3);

    prep_wt<<<NST * NST / 512, 512>>>(B, C);             // tf32 transposed weights
    gemm_scan1<<<CHUNKS, 128, SM1>>>(u, A);              // x1 + chunk sums
    scan_carry<<<BATCH, 128, SM2>>>(A, x0, tail, wt);    // carries + new_state
    gemm_scan2<<<CHUNKS, 128, SM3>>>(A, out);            // x (in SMEM) @ C -> y
}

// round 16
// speedup vs baseline: 1.0796x; 1.0796x over previous
#include <cuda_runtime.h>
#include <cstdint>

// Problem constants (fixed by setup_inputs)
#define BATCH   8
#define LEN     4096
#define ROWS    (BATCH * LEN)      // 32768
#define NST     256                // state/input/output size
#define KHALF   128                // number of 2x2 complex channels
#define LC      64                 // scan chunk length == GEMM block M tile
#define CHUNKS  (ROWS / LC)        // 512
#define CPB     (LEN / LC)         // 64 chunks per batch sequence

// Scratch (device globals: no allocation allowed)
__device__ float g_x1[ROWS * NST];     // u @ B (f32)
__device__ float g_s [CHUNKS * NST];   // per-chunk local scan results
__device__ float g_in[CHUNKS * NST];   // per-chunk incoming states
__device__ float g_Bt[NST * NST];      // B^T, tf32(rna)  [n][k]
__device__ float g_Ct[NST * NST];      // C^T, tf32(rna)  [n][k]

// ---------------------------------------------------------------------------
// helpers
// ---------------------------------------------------------------------------
__device__ __forceinline__ uint32_t f2tf(float f) {
    uint32_t r;
    asm("cvt.rna.tf32.f32 %0, %1;" : "=r"(r) : "f"(f));
    return r;
}

__device__ __forceinline__ void mma4(float* d, const uint32_t* a, uint32_t b0, uint32_t b1) {
    asm volatile(
        "mma.sync.aligned.m16n8k8.row.col.f32.tf32.tf32.f32 "
        "{%0,%1,%2,%3}, {%4,%5,%6,%7}, {%8,%9}, {%0,%1,%2,%3};\n"
        : "+f"(d[0]), "+f"(d[1]), "+f"(d[2]), "+f"(d[3])
        : "r"(a[0]), "r"(a[1]), "r"(a[2]), "r"(a[3]), "r"(b0), "r"(b1));
}

__device__ __forceinline__ void ldsm4(uint32_t* r, uint32_t addr) {
    asm volatile("ldmatrix.sync.aligned.m8n8.x4.shared.b16 {%0,%1,%2,%3}, [%4];"
                 : "=r"(r[0]), "=r"(r[1]), "=r"(r[2]), "=r"(r[3]) : "r"(addr));
}

__device__ __forceinline__ void cp16(uint32_t smem, const void* gmem) {
    asm volatile("cp.async.ca.shared.global [%0], [%1], 16;\n" :: "r"(smem), "l"(gmem));
}

// ===========================================================================
// prep: weights -> transposed tf32(rna) copies. Coalesced read, strided write.
// ===========================================================================
__global__ void prep_wt(const float* __restrict__ B, const float* __restrict__ C) {
    int i = blockIdx.x * blockDim.x + threadIdx.x;   // i = k*256 + n
    int k = i >> 8, n = i & 255;
    g_Bt[n * NST + k] = __uint_as_float(f2tf(B[i]));
    g_Ct[n * NST + k] = __uint_as_float(f2tf(C[i]));
}

// ===========================================================================
// K1: gemm1 (x1 = u @ B) fused with per-chunk zero-init local scan -> g_s.
// Block tile 64x256, BK=16, 256 threads / 8 warps, warp tile 64x32 (warps
// share A). Fragments via ldmatrix.x4.b16; B^T preconverted to tf32.
// SMEM: As[2][64][20] + BsT[2][256][20] = 51200 B; xs alias 64x258 = 66048 B.
// ===========================================================================
__global__ void __launch_bounds__(256, 2) gemm_scan1(const float* __restrict__ u,
                                                     const float* __restrict__ Arot)
{
    extern __shared__ float sm1[];
    float (*As)[64][20]  = (float(*)[64][20])sm1;            // [2][64][20]
    float (*Bs)[256][20] = (float(*)[256][20])(sm1 + 2560);  // [2][256][20]
    float (*xs)[258]     = (float(*)[258])sm1;               // alias (epilogue)

    const int tid  = threadIdx.x;
    const int warp = tid >> 5;
    const int lane = tid & 31;
    const int g = lane >> 2, t = lane & 3;
    const long mbase = (long)blockIdx.x * 64;
    const int nb0 = warp * 32;

    // ldmatrix per-lane address components
    const int aRow = (lane & 7) + ((lane >> 3) & 1) * 8;
    const int aCol = (lane >> 4) * 4;
    const int bRow = (lane & 7) + (lane >> 4) * 8;
    const int bCol = ((lane >> 3) & 1) * 4;

    auto loadTiles = [&](int k0, int st) {
        {                                                // A: 256 x 16B chunks
            int r = tid >> 2, c4 = (tid & 3) * 4;
            cp16((uint32_t)__cvta_generic_to_shared(&As[st][r][c4]),
                 u + (mbase + r) * NST + k0 + c4);
        }
        #pragma unroll
        for (int p = 0; p < 4; ++p) {                    // B^T: 1024 x 16B chunks
            int ch = tid + p * 256;
            int n = ch >> 2, c4 = (ch & 3) * 4;
            cp16((uint32_t)__cvta_generic_to_shared(&Bs[st][n][c4]),
                 g_Bt + n * NST + k0 + c4);
        }
        asm volatile("cp.async.commit_group;\n");
    };

    float acc[4][4][4];
    #pragma unroll
    for (int i = 0; i < 4; ++i)
        #pragma unroll
        for (int j = 0; j < 4; ++j)
            #pragma unroll
            for (int q = 0; q < 4; ++q) acc[i][j][q] = 0.f;

    loadTiles(0, 0);

    for (int it = 0; it < 16; ++it) {
        asm volatile("cp.async.wait_group 0;\n");
        __syncthreads();
        if (it + 1 < 16) loadTiles((it + 1) * 16, (it + 1) & 1);

        const int st = it & 1;
        // convert the A stage in place: f32 -> tf32(rna). 1024 floats / 256 thr.
        {
            int r = tid >> 2, c = (tid & 3) * 4;
            float4 v = *(float4*)&As[st][r][c];
            v.x = __uint_as_float(f2tf(v.x));
            v.y = __uint_as_float(f2tf(v.y));
            v.z = __uint_as_float(f2tf(v.z));
            v.w = __uint_as_float(f2tf(v.w));
            *(float4*)&As[st][r][c] = v;
        }
        __syncthreads();

        const uint32_t sA = (uint32_t)__cvta_generic_to_shared(&As[st][0][0]);
        const uint32_t sB = (uint32_t)__cvta_generic_to_shared(&Bs[st][0][0]);
        #pragma unroll
        for (int kk = 0; kk < 16; kk += 8) {
            uint32_t bq[2][4];
            #pragma unroll
            for (int q = 0; q < 2; ++q)
                ldsm4(bq[q], sB + ((nb0 + 16 * q + bRow) * 20 + kk + bCol) * 4);
            uint32_t aa[4][4];
            #pragma unroll
            for (int ii = 0; ii < 4; ++ii)
                ldsm4(aa[ii], sA + ((ii * 16 + aRow) * 20 + kk + aCol) * 4);
            #pragma unroll
            for (int ii = 0; ii < 4; ++ii)
                #pragma unroll
                for (int q = 0; q < 2; ++q) {
                    mma4(acc[ii][2 * q],     aa[ii], bq[q][0], bq[q][1]);
                    mma4(acc[ii][2 * q + 1], aa[ii], bq[q][2], bq[q][3]);
                }
        }
    }
    __syncthreads();   // before epilogue writes alias the mainloop buffers

    // Epilogue: write x1 tile to gmem AND into xs (alias).
    #pragma unroll
    for (int i = 0; i < 4; ++i) {
        long r0 = mbase + i * 16 + g;
        int lr = i * 16 + g;
        #pragma unroll
        for (int j = 0; j < 4; ++j) {
            int cn = nb0 + j * 8 + 2 * t;
            float2 v0 = make_float2(acc[i][j][0], acc[i][j][1]);
            float2 v1 = make_float2(acc[i][j][2], acc[i][j][3]);
            *(float2*)&g_x1[r0 * NST + cn]       = v0;
            *(float2*)&g_x1[(r0 + 8) * NST + cn] = v1;
            *(float2*)&xs[lr][cn]     = v0;
            *(float2*)&xs[lr + 8][cn] = v1;
        }
    }
    __syncthreads();

    // Local scan (zero init): thread k handles complex channel k.
    if (tid < KHALF) {
        const int k = tid;
        const float wc = Arot[k * 4 + 0];
        const float ws = Arot[k * 4 + 1];
        float zr = 0.f, zi = 0.f;
        #pragma unroll 8
        for (int tt = 0; tt < LC; ++tt) {
            float2 v = *(const float2*)&xs[tt][2 * k];
            float nr = fmaf(zr, wc, fmaf(-zi, ws, v.x));
            float ni = fmaf(zr, ws, fmaf( zi, wc, v.y));
            zr = nr; zi = ni;
        }
        ((float2*)g_s)[blockIdx.x * KHALF + k] = make_float2(zr, zi);
    }
}

// ===========================================================================
// K2: carry propagation, one block per batch (SMEM-staged chain).
// ===========================================================================
__global__ void __launch_bounds__(128) scan_carry(const float* __restrict__ Arot,
                                                  const float* __restrict__ x0,
                                                  float* __restrict__ tail,
                                                  int write_tail)
{
    extern __shared__ float ss[];               // [64][256]
    const int b = blockIdx.x;
    const int k = threadIdx.x;                  // 0..127

    const float4* src = (const float4*)(g_s + (size_t)b * CPB * NST);
    float4* dst = (float4*)ss;
    #pragma unroll
    for (int i = 0; i < 32; ++i)
        dst[k + i * 128] = src[k + i * 128];
    __syncthreads();

    float Wr = Arot[k * 4 + 0];
    float Wi = Arot[k * 4 + 1];
    #pragma unroll
    for (int i = 0; i < 6; ++i) {               // w -> w^64 by squaring
        float nr = Wr * Wr - Wi * Wi;
        float ni = 2.f * Wr * Wi;
        Wr = nr; Wi = ni;
    }

    float2 z = ((const float2*)x0)[b * KHALF + k];
    float zr = z.x, zi = z.y;
    #pragma unroll 8
    for (int c = 0; c < CPB; ++c) {
        ((float2*)g_in)[(b * CPB + c) * KHALF + k] = make_float2(zr, zi);
        float2 s = ((const float2*)ss)[c * KHALF + k];
        float nr = fmaf(zr, Wr, fmaf(-zi, Wi, s.x));
        float ni = fmaf(zr, Wi, fmaf( zi, Wr, s.y));
        zr = nr; zi = ni;
    }
    if (write_tail)
        ((float2*)tail)[b * KHALF + k] = make_float2(zr, zi);
}

// ===========================================================================
// K3: fused apply-scan + gemm2 (y = x @ C).
// 256 threads / 8 warps, warp tile 64x32. Scan writes x tf32(rna)-rounded
// into xs[64][260]; mainloop ldmatrix's A from xs, B from preconverted C^T.
// SMEM: xs 64x260 (66560 B) + Bs[2][256][20] (40960 B) = 107520 B -> 2 blk/SM.
// ===========================================================================
__global__ void __launch_bounds__(256, 2) gemm_scan2(const float* __restrict__ Arot,
                                                     float* __restrict__ y)
{
    extern __shared__ float sm3[];
    float (*xs)[260]     = (float(*)[260])sm3;                 // 64 x 260
    float (*Bs)[256][20] = (float(*)[256][20])(sm3 + 64*260);  // [2][256][20]

    const int tid  = threadIdx.x;
    const int warp = tid >> 5;
    const int lane = tid & 31;
    const int g = lane >> 2, t = lane & 3;
    const int cid = blockIdx.x;
    const long mbase = (long)cid * 64;
    const int nb0 = warp * 32;

    const int aRow = (lane & 7) + ((lane >> 3) & 1) * 8;
    const int aCol = (lane >> 4) * 4;
    const int bRow = (lane & 7) + (lane >> 4) * 8;
    const int bCol = ((lane >> 3) & 1) * 4;

    auto loadB = [&](int k0, int st) {
        #pragma unroll
        for (int p = 0; p < 4; ++p) {
            int ch = tid + p * 256;
            int n = ch >> 2, c4 = (ch & 3) * 4;
            cp16((uint32_t)__cvta_generic_to_shared(&Bs[st][n][c4]),
                 g_Ct + n * NST + k0 + c4);
        }
        asm volatile("cp.async.commit_group;\n");
    };

    loadB(0, 0);   // overlap first C tile with the scan below

    // ---- apply-scan: gmem x1 -> recurrence -> xs (tf32-rounded) ----
    if (tid < KHALF) {
        const int k = tid;
        const float wc = Arot[k * 4 + 0];
        const float ws = Arot[k * 4 + 1];
        const float2* p = (const float2*)(g_x1 + (size_t)cid * LC * NST) + k;
        float2 z0 = ((const float2*)g_in)[cid * KHALF + k];
        float zr = z0.x, zi = z0.y;
        #pragma unroll
        for (int tt0 = 0; tt0 < LC; tt0 += 8) {
            float2 v[8];
            #pragma unroll
            for (int j = 0; j < 8; ++j)
                v[j] = p[(size_t)(tt0 + j) * (NST / 2)];
            #pragma unroll
            for (int j = 0; j < 8; ++j) {
                float nr = fmaf(zr, wc, fmaf(-zi, ws, v[j].x));
                float ni = fmaf(zr, ws, fmaf( zi, wc, v[j].y));
                zr = nr; zi = ni;
                *(float2*)&xs[tt0 + j][2 * k] =
                    make_float2(__uint_as_float(f2tf(zr)), __uint_as_float(f2tf(zi)));
            }
        }
    }

    // ---- mainloop: y_tile = xs @ C ----
    float acc[4][4][4];
    #pragma unroll
    for (int i = 0; i < 4; ++i)
        #pragma unroll
        for (int j = 0; j < 4; ++j)
            #pragma unroll
            for (int q = 0; q < 4; ++q) acc[i][j][q] = 0.f;

    const uint32_t sX = (uint32_t)__cvta_generic_to_shared(&xs[0][0]);

    for (int it = 0; it < 16; ++it) {
        asm volatile("cp.async.wait_group 0;\n");
        __syncthreads();                       // also orders scan writes (it==0)
        if (it + 1 < 16) loadB((it + 1) * 16, (it + 1) & 1);

        const int st = it & 1;
        const int k0 = it * 16;
        const uint32_t sB = (uint32_t)__cvta_generic_to_shared(&Bs[st][0][0]);
        #pragma unroll
        for (int kk = 0; kk < 16; kk += 8) {
            uint32_t bq[2][4];
            #pragma unroll
            for (int q = 0; q < 2; ++q)
                ldsm4(bq[q], sB + ((nb0 + 16 * q + bRow) * 20 + kk + bCol) * 4);
            uint32_t aa[4][4];
            #pragma unroll
            for (int ii = 0; ii < 4; ++ii)
                ldsm4(aa[ii], sX + ((ii * 16 + aRow) * 260 + k0 + kk + aCol) * 4);
            #pragma unroll
            for (int ii = 0; ii < 4; ++ii)
                #pragma unroll
                for (int q = 0; q < 2; ++q) {
                    mma4(acc[ii][2 * q],     aa[ii], bq[q][0], bq[q][1]);
                    mma4(acc[ii][2 * q + 1], aa[ii], bq[q][2], bq[q][3]);
                }
        }
    }

    #pragma unroll
    for (int i = 0; i < 4; ++i) {
        long r0 = mbase + i * 16 + g;
        #pragma unroll
        for (int j = 0; j < 4; ++j) {
            int cn = nb0 + j * 8 + 2 * t;
            *(float2*)&y[r0 * NST + cn]       = make_float2(acc[i][j][0], acc[i][j][1]);
            *(float2*)&y[(r0 + 8) * NST + cn] = make_float2(acc[i][j][2], acc[i][j][3]);
        }
    }
}

// ---------------------------------------------------------------------------
// Launch: prep -> K1 -> K2 -> K3.
// Output: y (8*4096*256 f32) then new_state (8*128*2 f32), concatenated.
// ---------------------------------------------------------------------------
extern "C" void kernel_launch(void* const* d_in, const int* in_sizes, int n_in,
                              void* d_out, int out_size)
{
    const float* u  = (const float*)d_in[0];
    const float* x0 = (const float*)d_in[1];
    const float* A  = (const float*)d_in[2];
    const float* B  = (const float*)d_in[3];
    const float* C  = (const float*)d_in[4];
    float* out = (float*)d_out;

    const int YSZ = ROWS * NST;
    const int TSZ = BATCH * KHALF * 2;
    const int wt = (out_size >= YSZ + TSZ) ? 1 : 0;
    float* tail = out + YSZ;

    const int SM1 = 66048;     // xs alias dominates (As+BsT = 51200)
    const int SM2 = 65536;     // ss[64][256]
    const int SM3 = 107520;    // xs[64][260] + BsT 2-stage

    cudaFuncSetAttribute(gemm_scan1, cudaFuncAttributeMaxDynamicSharedMemorySize, SM1);
    cudaFuncSetAttribute(scan_carry, cudaFuncAttributeMaxDynamicSharedMemorySize, SM2);
    cudaFuncSetAttribute(gemm_scan2, cudaFuncAttributeMaxDynamicSharedMemorySize, SM3);

    prep_wt<<<NST * NST / 512, 512>>>(B, C);             // tf32 transposed weights
    gemm_scan1<<<CHUNKS, 256, SM1>>>(u, A);              // x1 + chunk sums
    scan_carry<<<BATCH, 128, SM2>>>(A, x0, tail, wt);    // carries + new_state
    gemm_scan2<<<CHUNKS, 256, SM3>>>(A, out);            // x (in SMEM) @ C -> y
}